// round 6
// baseline (speedup 1.0000x reference)
#include <cuda_runtime.h>
#include <cuda_bf16.h>
#include <cstdint>

#define B 4
#define L 512
#define D 128
#define ROWS 8           // queries per block
#define KR (ROWS + 2)    // k rows incl. halo
#define XT 12            // padded transposed row length
#define SD 8             // d-rows per weight stage
#define NSTAGE (D / SD)  // 16
#define EPSV 1e-8f

__device__ __forceinline__ void cp_async16(void* dst, const void* src) {
    unsigned int s = (unsigned int)__cvta_generic_to_shared(dst);
    asm volatile("cp.async.ca.shared.global [%0], [%1], 16;" :: "r"(s), "l"(src));
}
__device__ __forceinline__ void cp_commit() {
    asm volatile("cp.async.commit_group;");
}
template<int N>
__device__ __forceinline__ void cp_wait() {
    asm volatile("cp.async.wait_group %0;" :: "n"(N));
}

// accurate tanh: 1 - 2/(e^{2x}+1)
__device__ __forceinline__ float tanh_acc(float x) {
    float e2 = __expf(2.0f * x);
    return 1.0f - __fdividef(2.0f, e2 + 1.0f);
}

// ---------------------------------------------------------------------------
// Fully fused, cp.async-staged weights.
// grid: (L/ROWS, B) = (64, 4); 256 threads (warps 0-3: q cols, 4-7: k cols)
// ---------------------------------------------------------------------------
__global__ __launch_bounds__(256) void fused_kernel(
    const float* __restrict__ X,  const float* __restrict__ Wt,
    const float* __restrict__ Wx, const float* __restrict__ Wa,
    const float* __restrict__ bh, const float* __restrict__ ba_p,
    float* __restrict__ out)
{
    __shared__ float Xs [KR][D];          // row-major (output phase)
    __shared__ float XsT[D][XT];          // transposed (GEMM broadcasts)
    __shared__ float WS [2][2][SD][D];    // [buf][Wt=0/Wx=1][d][c]
    __shared__ float qs [ROWS][D];
    __shared__ float ks [KR][D];

    const int b   = blockIdx.y;
    const int q0  = blockIdx.x * ROWS;
    const int tid = threadIdx.x;
    const float* XB = X + b * L * D;

    // weight staging addressing: 256 threads cover 8 rows x 32 float4 chunks
    const int wrow = tid >> 5;
    const int wc4  = (tid & 31) * 4;

    // prologue: stage 0 weights in flight while we load the X tile
    cp_async16(&WS[0][0][wrow][wc4], Wt + wrow * D + wc4);
    cp_async16(&WS[0][1][wrow][wc4], Wx + wrow * D + wc4);
    cp_commit();

    // ---- load X tile (rows clamped at batch edge; masked later), both layouts
    #pragma unroll
    for (int i = tid; i < KR * (D / 4); i += 256) {
        int r = i >> 5, d4 = i & 31;
        int row = min(max(q0 - 1 + r, 0), L - 1);
        float4 v = ((const float4*)(XB + row * D))[d4];
        ((float4*)&Xs[r][0])[d4] = v;
        XsT[d4 * 4 + 0][r] = v.x;
        XsT[d4 * 4 + 1][r] = v.y;
        XsT[d4 * 4 + 2][r] = v.z;
        XsT[d4 * 4 + 3][r] = v.w;
    }

    const int c = tid & 127;
    const bool isq = (tid < 128);        // warp-uniform

    float acc[KR];
    #pragma unroll
    for (int r = 0; r < KR; r++) acc[r] = 0.f;

    for (int s = 0; s < NSTAGE; s++) {
        if (s + 1 < NSTAGE) {
            int nb = (s + 1) & 1;
            cp_async16(&WS[nb][0][wrow][wc4], Wt + ((s + 1) * SD + wrow) * D + wc4);
            cp_async16(&WS[nb][1][wrow][wc4], Wx + ((s + 1) * SD + wrow) * D + wc4);
            cp_commit();
            cp_wait<1>();
        } else {
            cp_wait<0>();
        }
        __syncthreads();

        const int bf = s & 1;
        const float* wcol = &WS[bf][isq ? 0 : 1][0][c];
        #pragma unroll
        for (int dd = 0; dd < SD; dd++) {
            const int d = s * SD + dd;
            float w = wcol[dd * D];
            float4 xa = *(const float4*)&XsT[d][0];
            float4 xb = *(const float4*)&XsT[d][4];
            float4 xc = *(const float4*)&XsT[d][8];
            if (isq) {
                // q rows 1..8 of the tile
                acc[0] = fmaf(xa.y, w, acc[0]);
                acc[1] = fmaf(xa.z, w, acc[1]);
                acc[2] = fmaf(xa.w, w, acc[2]);
                acc[3] = fmaf(xb.x, w, acc[3]);
                acc[4] = fmaf(xb.y, w, acc[4]);
                acc[5] = fmaf(xb.z, w, acc[5]);
                acc[6] = fmaf(xb.w, w, acc[6]);
                acc[7] = fmaf(xc.x, w, acc[7]);
            } else {
                // k rows 0..9
                acc[0] = fmaf(xa.x, w, acc[0]);
                acc[1] = fmaf(xa.y, w, acc[1]);
                acc[2] = fmaf(xa.z, w, acc[2]);
                acc[3] = fmaf(xa.w, w, acc[3]);
                acc[4] = fmaf(xb.x, w, acc[4]);
                acc[5] = fmaf(xb.y, w, acc[5]);
                acc[6] = fmaf(xb.z, w, acc[6]);
                acc[7] = fmaf(xb.w, w, acc[7]);
                acc[8] = fmaf(xc.x, w, acc[8]);
                acc[9] = fmaf(xc.y, w, acc[9]);
            }
        }
        __syncthreads();
    }

    if (isq) {
        const float bhc = bh[c];
        #pragma unroll
        for (int r = 0; r < ROWS; r++) qs[r][c] = acc[r] + bhc;
    } else {
        #pragma unroll
        for (int r = 0; r < KR; r++) ks[r][c] = acc[r];
    }
    __syncthreads();

    // ---- window phase: warp == query (8 warps, 8 queries) ----
    const int rq   = tid >> 5;
    const int lane = tid & 31;
    const int qi   = q0 + rq;
    const float4 wv = ((const float4*)Wa)[lane];
    const float bav = ba_p[0];
    const float4 qv = ((const float4*)&qs[rq][0])[lane];

    float e[3];
    #pragma unroll
    for (int tt = 0; tt < 3; tt++) {
        int j = qi - 1 + tt;
        float4 kv = ((const float4*)&ks[rq + tt][0])[lane];
        float p = tanh_acc(qv.x + kv.x) * wv.x
                + tanh_acc(qv.y + kv.y) * wv.y
                + tanh_acc(qv.z + kv.z) * wv.z
                + tanh_acc(qv.w + kv.w) * wv.w;
        #pragma unroll
        for (int o = 16; o > 0; o >>= 1)
            p += __shfl_xor_sync(0xffffffffu, p, o);
        e[tt] = (j >= 0 && j < L) ? (p + bav) : -1e30f;
    }

    float m  = fmaxf(e[0], fmaxf(e[1], e[2]));
    float w0 = __expf(e[0] - m);
    float w1 = __expf(e[1] - m);
    float w2 = __expf(e[2] - m);
    float inv = __fdividef(1.0f, w0 + w1 + w2 + EPSV);

    float4 o4 = make_float4(0.f, 0.f, 0.f, 0.f);
    #pragma unroll
    for (int tt = 0; tt < 3; tt++) {
        float w = (tt == 0) ? w0 : (tt == 1) ? w1 : w2;
        float a = w * inv;
        float4 xv = ((const float4*)&Xs[rq + tt][0])[lane];
        o4.x = fmaf(a, xv.x, o4.x);
        o4.y = fmaf(a, xv.y, o4.y);
        o4.z = fmaf(a, xv.z, o4.z);
        o4.w = fmaf(a, xv.w, o4.w);
    }
    ((float4*)(out + (b * L + qi) * D))[lane] = o4;
}

extern "C" void kernel_launch(void* const* d_in, const int* in_sizes, int n_in,
                              void* d_out, int out_size)
{
    const float* X  = (const float*)d_in[0];
    const float* Wt = (const float*)d_in[1];
    const float* Wx = (const float*)d_in[2];
    const float* Wa = (const float*)d_in[3];
    const float* bh = (const float*)d_in[4];
    const float* ba = (const float*)d_in[5];
    float* out = (float*)d_out;

    dim3 grid(L / ROWS, B);
    fused_kernel<<<grid, 256>>>(X, Wt, Wx, Wa, bh, ba, out);
}

// round 7
// speedup vs baseline: 1.1002x; 1.1002x over previous
#include <cuda_runtime.h>
#include <cuda_bf16.h>
#include <cstdint>

#define B 4
#define L 512
#define D 128
#define QT 16            // queries per block
#define EPSV 1e-8f

typedef unsigned long long ull;

// ---- smem carve (floats) ----
#define OFF_WXS 0
#define OFF_WTS 16384
#define OFF_XST 32768          // [128][20]
#define OFF_XS  35328          // [18][128]
#define OFF_QKS 37632          // [18][128]  k rows 0..17 (tile)
#define OFF_QQS 39936          // [16][128]  q rows 0..15
#define SMEM_FLOATS 41984
#define SMEM_BYTES (SMEM_FLOATS * 4)

__device__ __forceinline__ void cp_async16(void* dst, const void* src) {
    unsigned int s = (unsigned int)__cvta_generic_to_shared(dst);
    asm volatile("cp.async.ca.shared.global [%0], [%1], 16;" :: "r"(s), "l"(src));
}
__device__ __forceinline__ void cp_commit() {
    asm volatile("cp.async.commit_group;");
}
__device__ __forceinline__ void cp_wait0() {
    asm volatile("cp.async.wait_group 0;");
}

__device__ __forceinline__ ull ffma2(ull a, ull b, ull c) {
    ull d;
    asm("fma.rn.f32x2 %0, %1, %2, %3;" : "=l"(d) : "l"(a), "l"(b), "l"(c));
    return d;
}
__device__ __forceinline__ ull dup2(float x) {
    ull d;
    unsigned int u = __float_as_uint(x);
    asm("mov.b64 %0, {%1, %1};" : "=l"(d) : "r"(u));
    return d;
}

// accurate tanh: 1 - 2/(e^{2x}+1)
__device__ __forceinline__ float tanh_acc(float x) {
    float e2 = __expf(2.0f * x);
    return 1.0f - __fdividef(2.0f, e2 + 1.0f);
}

// ---------------------------------------------------------------------------
// One block per 16 queries: stage full Wt/Wx in smem, packed-f32x2 GEMM for
// q (16 rows) + k (18 rows incl. halo), then window softmax + output.
// grid: (L/QT, B) = (32, 4) = 128 blocks; 512 threads.
// ---------------------------------------------------------------------------
__global__ __launch_bounds__(512, 1) void fused_kernel(
    const float* __restrict__ X,  const float* __restrict__ Wt,
    const float* __restrict__ Wx, const float* __restrict__ Wa,
    const float* __restrict__ bh, const float* __restrict__ ba_p,
    float* __restrict__ out)
{
    extern __shared__ float sm[];
    float* Wxs = sm + OFF_WXS;   // [d][c] row-major, 128x128
    float* Wts = sm + OFF_WTS;
    float* XsT = sm + OFF_XST;   // [d][20]: 0..15 = X rows q0..q0+15,
                                 //          16 = X[q0-1], 17 = X[q0+16] (clamped)
    float* Xs  = sm + OFF_XS;    // [r][128], tile rows 0..17 = X[q0-1 .. q0+16]
    float* qks = sm + OFF_QKS;   // k for tile rows 0..17
    float* qqs = sm + OFF_QQS;   // q (no bh) rows 0..15

    const int b   = blockIdx.y;
    const int q0  = blockIdx.x * QT;
    const int tid = threadIdx.x;
    const float* XB = X + b * L * D;

    // ---- stage both weight matrices via cp.async (8192 float4 chunks) ----
    {
        const float4* Wx4 = (const float4*)Wx;
        const float4* Wt4 = (const float4*)Wt;
        #pragma unroll
        for (int j = 0; j < 8; j++) {
            int idx = j * 512 + tid;
            cp_async16(Wxs + idx * 4, Wx4 + idx);
            cp_async16(Wts + idx * 4, Wt4 + idx);
        }
        cp_commit();
    }

    // ---- X tile: 18 rows (q0-1 .. q0+16, clamped), row-major + transposed ----
    for (int i = tid; i < 18 * 32; i += 512) {
        int r  = i >> 5;           // 0..17 tile row
        int d4 = i & 31;
        int row = min(max(q0 - 1 + r, 0), L - 1);
        float4 v = ((const float4*)(XB + row * D))[d4];
        ((float4*)(Xs + r * D))[d4] = v;
        int slot = (r == 0) ? 16 : (r == 17) ? 17 : (r - 1);
        XsT[(d4 * 4 + 0) * 20 + slot] = v.x;
        XsT[(d4 * 4 + 1) * 20 + slot] = v.y;
        XsT[(d4 * 4 + 2) * 20 + slot] = v.z;
        XsT[(d4 * 4 + 3) * 20 + slot] = v.w;
    }

    cp_wait0();
    __syncthreads();

    // ---- GEMM phase ----
    if (tid < 128) {
        // main: 32 virtual rows (k tile-rows 1..16, q rows 0..15), tile 4r x 8c
        const int rg = tid >> 4;       // 0..7  (0-3: k, 4-7: q)
        const int cg = tid & 15;       // 8 cols each
        const float* Wp = ((rg < 4) ? Wxs : Wts) + cg * 8;
        const float* Xp = XsT + (rg & 3) * 4;

        ull acc[4][4];
        #pragma unroll
        for (int r = 0; r < 4; r++)
            #pragma unroll
            for (int p = 0; p < 4; p++) acc[r][p] = 0ull;

        #pragma unroll 4
        for (int d = 0; d < D; d++) {
            float4 xv = *(const float4*)(Xp + d * 20);
            ulonglong2 w01 = *(const ulonglong2*)(Wp + d * D);
            ulonglong2 w23 = *(const ulonglong2*)(Wp + d * D + 4);
            ull x0 = dup2(xv.x), x1 = dup2(xv.y), x2 = dup2(xv.z), x3 = dup2(xv.w);
            acc[0][0] = ffma2(x0, w01.x, acc[0][0]);
            acc[0][1] = ffma2(x0, w01.y, acc[0][1]);
            acc[0][2] = ffma2(x0, w23.x, acc[0][2]);
            acc[0][3] = ffma2(x0, w23.y, acc[0][3]);
            acc[1][0] = ffma2(x1, w01.x, acc[1][0]);
            acc[1][1] = ffma2(x1, w01.y, acc[1][1]);
            acc[1][2] = ffma2(x1, w23.x, acc[1][2]);
            acc[1][3] = ffma2(x1, w23.y, acc[1][3]);
            acc[2][0] = ffma2(x2, w01.x, acc[2][0]);
            acc[2][1] = ffma2(x2, w01.y, acc[2][1]);
            acc[2][2] = ffma2(x2, w23.x, acc[2][2]);
            acc[2][3] = ffma2(x2, w23.y, acc[2][3]);
            acc[3][0] = ffma2(x3, w01.x, acc[3][0]);
            acc[3][1] = ffma2(x3, w01.y, acc[3][1]);
            acc[3][2] = ffma2(x3, w23.x, acc[3][2]);
            acc[3][3] = ffma2(x3, w23.y, acc[3][3]);
        }

        float* outp = (rg < 4) ? (qks + (rg * 4 + 1) * D) : (qqs + (rg - 4) * 4 * D);
        #pragma unroll
        for (int r = 0; r < 4; r++)
            #pragma unroll
            for (int p = 0; p < 4; p++)
                *(ull*)&outp[r * D + cg * 8 + p * 2] = acc[r][p];
    } else if (tid < 256) {
        // halo: k tile-rows 0 and 17, 1 row x 2 cols per thread (4 warps)
        const int hw   = tid - 128;        // 0..127
        const int hrow = hw >> 6;          // 0 -> tile k row 0, 1 -> row 17
        const int half = (hw >> 5) & 1;
        const int c2   = hw & 31;
        const int col  = half * 64 + c2 * 2;
        const float* Wp = Wxs + col;
        const float* Xp = XsT + 16 + hrow;

        ull acc = 0ull;
        #pragma unroll 8
        for (int d = 0; d < D; d++) {
            ull xd = dup2(Xp[d * 20]);
            ull w  = *(const ull*)(Wp + d * D);
            acc = ffma2(xd, w, acc);
        }
        *(ull*)&qks[(hrow ? 17 : 0) * D + col] = acc;
    }
    __syncthreads();

    // ---- window phase: 16 warps, warp == query ----
    const int rq   = tid >> 5;        // 0..15
    const int lane = tid & 31;
    const int qi   = q0 + rq;

    float4 qv  = ((const float4*)(qqs + rq * D))[lane];
    float4 bhv = ((const float4*)bh)[lane];
    qv.x += bhv.x; qv.y += bhv.y; qv.z += bhv.z; qv.w += bhv.w;
    const float4 wv = ((const float4*)Wa)[lane];
    const float bav = ba_p[0];

    float e[3];
    #pragma unroll
    for (int tt = 0; tt < 3; tt++) {
        int j = qi - 1 + tt;                       // global key, tile row rq+tt
        float4 kv = ((const float4*)(qks + (rq + tt) * D))[lane];
        float p = tanh_acc(qv.x + kv.x) * wv.x
                + tanh_acc(qv.y + kv.y) * wv.y
                + tanh_acc(qv.z + kv.z) * wv.z
                + tanh_acc(qv.w + kv.w) * wv.w;
        #pragma unroll
        for (int o = 16; o > 0; o >>= 1)
            p += __shfl_xor_sync(0xffffffffu, p, o);
        e[tt] = (j >= 0 && j < L) ? (p + bav) : -1e30f;
    }

    float m  = fmaxf(e[0], fmaxf(e[1], e[2]));
    float w0 = __expf(e[0] - m);
    float w1 = __expf(e[1] - m);
    float w2 = __expf(e[2] - m);
    float inv = __fdividef(1.0f, w0 + w1 + w2 + EPSV);

    float4 o4 = make_float4(0.f, 0.f, 0.f, 0.f);
    #pragma unroll
    for (int tt = 0; tt < 3; tt++) {
        float w = (tt == 0) ? w0 : (tt == 1) ? w1 : w2;
        float a = w * inv;
        float4 xv = ((const float4*)(Xs + (rq + tt) * D))[lane];
        o4.x = fmaf(a, xv.x, o4.x);
        o4.y = fmaf(a, xv.y, o4.y);
        o4.z = fmaf(a, xv.z, o4.z);
        o4.w = fmaf(a, xv.w, o4.w);
    }
    ((float4*)(out + (b * L + qi) * D))[lane] = o4;
}

extern "C" void kernel_launch(void* const* d_in, const int* in_sizes, int n_in,
                              void* d_out, int out_size)
{
    const float* X  = (const float*)d_in[0];
    const float* Wt = (const float*)d_in[1];
    const float* Wx = (const float*)d_in[2];
    const float* Wa = (const float*)d_in[3];
    const float* bh = (const float*)d_in[4];
    const float* ba = (const float*)d_in[5];
    float* out = (float*)d_out;

    cudaFuncSetAttribute(fused_kernel,
                         cudaFuncAttributeMaxDynamicSharedMemorySize, SMEM_BYTES);
    dim3 grid(L / QT, B);
    fused_kernel<<<grid, 512, SMEM_BYTES>>>(X, Wt, Wx, Wa, bh, ba, out);
}